// round 17
// baseline (speedup 1.0000x reference)
#include <cuda_runtime.h>
#include <cstdint>

// ---------------------------------------------------------------------------
// ConvLocalBlock via legacy mma.sync.m16n8k8 tf32 (PTX compute_103-safe; the
// harness's PTX target has no 'a' suffix so tcgen05/TMEM are unavailable).
//
// Stage 1: y = relu(bn1(x_patches @ conv_w))      M=130048 K=320  N=256
// Stage 2: z[:,l,:] = relu(bn2(y_win @ lw[l]))    per l: M=256 K=1280 N=256
//
// R16 = R15 with the deadlock fixed: cp.async.mbarrier.arrive WITHOUT .noinc
// increments the pending count before the deferred arrive (net zero on the
// phase), so the 128-count full barriers never tripped. .noinc consumes one
// of the pre-registered arrivals. All parity/slot math unchanged (re-audited:
// full[p%3] completion p/3; empty producer-wait completion p/3-1).
//
// Pipeline: per-slot full (cp.async.mbarrier.arrive.noinc, count=128,
// acquire-wait = cross-thread visibility) + empty (normal arrive after last
// stage read) mbarriers; no __syncthreads in the main loop, warps drift
// within the 3-slot ring. Register double-buffered fragments (prefetch k8+1,
// tail prefetches next stage's k0).
//
// Geometry: CTA 128x128, 4 warps (2m x 2n of 64x64), NSTAGE=3, 2 CTAs/SM.
// Engine: raw-fp32-bits tf32 MMA (RZ truncation, product bias cancelled by
// TCORR in BN alpha), A via ldmatrix.x4.b16, B scalar LDS, BSTR=136.
// ---------------------------------------------------------------------------

#define FSZ   5
#define NB    256
#define LIN   512
#define CIN   64
#define UDIM  256
#define L1DIM 508
#define L2DIM 504
#define KCONV 320
#define KLOC  1280
#define BNEPS 0.001f
#define TCORR 1.0007045f              // cancels tf32 RZ-truncation product bias

#define NSTAGE  3
#define KC      32
#define AROWS   128                   // CTA M-tile
#define ASTR    36                    // A smem row stride (floats)
#define BSTR    136                   // B smem row stride (136%32==8: clean)
#define A_BYTES (AROWS * ASTR * 4)    // 18432
#define B_BYTES (KC * BSTR * 4)       // 17408
#define STAGE_BYTES (A_BYTES + B_BYTES) // 35840
#define SMEM_MBAR   0                 // 6 x 8B: full[0..2], empty[0..2]
#define SMEM_ALPHA  512
#define SMEM_BETA   1024
#define SMEM_STAGE0 1536
#define SMEM_TOTAL  (SMEM_STAGE0 + NSTAGE * STAGE_BYTES)  // 109056 (106.5 KB)

__device__ __align__(128) float g_y[(size_t)NB * L1DIM * UDIM];

// ---- PTX helpers -----------------------------------------------------------
__device__ __forceinline__ uint32_t smem_u32(const void* p) {
    uint32_t a;
    asm("{ .reg .u64 t; cvta.to.shared.u64 t, %1; cvt.u32.u64 %0, t; }"
        : "=r"(a) : "l"(p));
    return a;
}
#define CP_ASYNC16(dst, src) \
    asm volatile("cp.async.cg.shared.global [%0], [%1], 16;" \
                 :: "r"(dst), "l"(src) : "memory")
// arrive (consuming a pre-registered count) when THIS thread's prior
// cp.asyncs complete. .noinc is load-bearing: the default form increments
// the pending count first and nets to zero.
#define CP_ARRIVE(mbar) \
    asm volatile("cp.async.mbarrier.arrive.noinc.shared.b64 [%0];" \
                 :: "r"(mbar) : "memory")
#define MBAR_INIT(a, c) \
    asm volatile("mbarrier.init.shared.b64 [%0], %1;" :: "r"(a), "r"(c) : "memory")
#define MBAR_ARRIVE(a) \
    asm volatile("mbarrier.arrive.shared.b64 _, [%0];" :: "r"(a) : "memory")
#define MBAR_WAIT(a, ph) do {                                               \
    uint32_t _m = (a), _p = (ph), _d;                                       \
    asm volatile("{ .reg .pred p;"                                          \
        " mbarrier.try_wait.parity.acquire.cta.shared::cta.b64 p,[%1],%2;"  \
        " selp.b32 %0,1,0,p; }" : "=r"(_d) : "r"(_m), "r"(_p) : "memory");  \
    if (!_d) {                                                              \
        asm volatile("{ .reg .pred P1;\n"                                   \
        "W%=: mbarrier.try_wait.parity.acquire.cta.shared::cta.b64 P1,[%0],%1,0x989680;\n" \
        " @P1 bra.uni D%=;\n bra.uni W%=;\nD%=: }"                          \
        :: "r"(_m), "r"(_p) : "memory");                                    \
    } } while (0)

__device__ __forceinline__ void ldsm_x4(uint32_t* r, uint32_t addr) {
    asm volatile("ldmatrix.sync.aligned.m8n8.x4.shared.b16 {%0,%1,%2,%3}, [%4];"
                 : "=r"(r[0]), "=r"(r[1]), "=r"(r[2]), "=r"(r[3]) : "r"(addr));
}
__device__ __forceinline__ void mma8(float* d, const uint32_t* a, const uint32_t* b) {
    asm volatile("mma.sync.aligned.m16n8k8.row.col.f32.tf32.tf32.f32 "
                 "{%0,%1,%2,%3}, {%4,%5,%6,%7}, {%8,%9}, {%0,%1,%2,%3};"
                 : "+f"(d[0]), "+f"(d[1]), "+f"(d[2]), "+f"(d[3])
                 : "r"(a[0]), "r"(a[1]), "r"(a[2]), "r"(a[3]),
                   "r"(b[0]), "r"(b[1]));
}

// one pipeline-stage load (128 threads): A 128 rows x 32 floats + B 32 x 128
__device__ __forceinline__ void load_stage(uint32_t sb, const float* const* aptr,
                                           const float* bsrc0, int tid) {
    const int achunk = tid & 7;
    const int bchunk = tid & 31;
    #pragma unroll
    for (int p = 0; p < 8; p++) {
        int arow = (tid >> 3) + p * 16;
        uint32_t adst = sb + (uint32_t)(arow * ASTR + achunk * 4) * 4;
        CP_ASYNC16(adst, aptr[p] + achunk * 4);
    }
    const uint32_t sbB = sb + A_BYTES;
    #pragma unroll
    for (int p = 0; p < 8; p++) {
        int brow = (tid >> 5) + p * 4;
        uint32_t bdst = sbB + (uint32_t)(brow * BSTR + bchunk * 4) * 4;
        CP_ASYNC16(bdst, bsrc0 + (size_t)brow * UDIM + bchunk * 4);
    }
}

// ---------------------------------------------------------------------------
// MODE 0: conv stage.  grid (1016 m-tiles, 2 n-tiles).   A=x, out=g_y
// MODE 1: local stage. grid (2 m, 2 n, 504 l).           A=g_y, out=z
// ---------------------------------------------------------------------------
template <int MODE>
__global__ void __launch_bounds__(128, 2)
gemm_mma(const float* __restrict__ Ain, const float* __restrict__ Bmat0,
         const float* __restrict__ bias, const float* __restrict__ gg,
         const float* __restrict__ bbn, const float* __restrict__ mmn,
         const float* __restrict__ vvn, float* __restrict__ outp)
{
    extern __shared__ char smem[];
    const uint32_t sbase = smem_u32(smem);
    const uint32_t sb0   = sbase + SMEM_STAGE0;
    const uint32_t mb_full  = sbase + SMEM_MBAR;        // full[i]  at +8i
    const uint32_t mb_empty = sbase + SMEM_MBAR + 24;   // empty[i] at +24+8i
    const int tid  = threadIdx.x;
    const int wid  = tid >> 5;
    const int lane = tid & 31;
    const int wm   = wid & 1;          // warp m index (0..1), 64 rows each
    const int wn   = wid >> 1;         // warp n index (0..1), 64 cols each
    const int g    = lane >> 2;
    const int tg   = lane & 3;

    const int S   = MODE ? (KLOC / KC) : (KCONV / KC);
    const int l   = MODE ? blockIdx.z : 0;
    const int mb0 = blockIdx.x * AROWS;
    const int n0  = blockIdx.y * 128;

    const float* Bmat = MODE ? (Bmat0 + (size_t)l * KLOC * UDIM) : Bmat0;
    float* out = MODE ? outp : g_y;

    // mbarrier init (before any arrive)
    if (tid == 0) {
        #pragma unroll
        for (int i = 0; i < NSTAGE; i++) {
            MBAR_INIT(mb_full + i * 8, 128);
            MBAR_INIT(mb_empty + i * 8, 128);
        }
    }
    // BN alpha/beta (alpha carries the tf32-truncation bias correction)
    {
        int n = n0 + tid;
        float a_ = gg[n] * rsqrtf(vvn[n] + BNEPS);
        float bi = MODE ? bias[(size_t)l * UDIM + n] : bias[n];
        ((float*)(smem + SMEM_ALPHA))[tid] = a_ * TCORR;
        ((float*)(smem + SMEM_BETA))[tid]  = bbn[n] + (bi - mmn[n]) * a_;
    }
    __syncthreads();   // publishes mbarrier init + alpha/beta (read in epilogue)

    // per-thread A row pointers for the 8 load passes
    const float* aptr[8];
    #pragma unroll
    for (int p = 0; p < 8; p++) {
        int r = (tid >> 3) + p * 16;
        if (MODE) {
            aptr[p] = g_y + ((size_t)(mb0 + r) * L1DIM + l) * UDIM;
        } else {
            unsigned gm = mb0 + r;
            unsigned b  = gm / L1DIM;
            unsigned t  = gm - b * L1DIM;
            aptr[p] = Ain + ((size_t)b * LIN + t) * CIN;
        }
    }

    // pipeline prologue: produce stages 0 and 1 (slots 0, 1; first slot use
    // -> no empty wait)
    #pragma unroll
    for (int p = 0; p < NSTAGE - 1; p++) {
        load_stage(sb0 + p * STAGE_BYTES, aptr, Bmat + (size_t)(p * KC) * UDIM + n0, tid);
        #pragma unroll
        for (int i = 0; i < 8; i++) aptr[i] += KC;
        CP_ARRIVE(mb_full + p * 8);
    }

    float acc[4][8][4] = {};

    // ldmatrix lane->tile-row mapping for A fragments (4 m-frags of 16 rows)
    const int trow = (lane & 7) + ((lane >> 3) & 1) * 8;
    const int tk   = (lane >> 4) * 4;
    int a_lm_off[4];
    #pragma unroll
    for (int mf = 0; mf < 4; mf++)
        a_lm_off[mf] = (wm * 64 + mf * 16 + trow) * ASTR + tk;
    const int boff = tg * BSTR + wn * 64 + g;   // B fragment base (floats)

    // double-buffered fragments; buffer index = k8&1 (compile-time)
    uint32_t af[2][4][4];
    uint32_t bf[2][8][2];

    auto frags = [&](int d, uint32_t stg, const uint32_t* bB, int kk) {
        #pragma unroll
        for (int mf = 0; mf < 4; mf++)
            ldsm_x4(af[d][mf], stg + (uint32_t)(a_lm_off[mf] + kk) * 4);
        #pragma unroll
        for (int jf = 0; jf < 8; jf++) {
            const uint32_t* p0 = bB + kk * BSTR + jf * 8;
            bf[d][jf][0] = p0[0];
            bf[d][jf][1] = p0[4 * BSTR];
        }
    };

    // prime: stage 0 full (completion 0, parity 0) -> buffer 0 = (stage 0, k0)
    MBAR_WAIT(mb_full + 0, 0u);
    {
        const uint32_t* bB0 = (const uint32_t*)(smem + SMEM_STAGE0 + A_BYTES) + boff;
        frags(0, sb0, bB0, 0);
    }

    // Main loop. Stage p -> slot p%3, full completion index p/3.
    //  * full[s] confirmed by iter s-1's tail wait (or the prime).
    //  * producer for p=s+2 waits empty[p%3] completion p/3-1, loads,
    //    cp-arrives full[p%3].
    //  * tail prefetch waits full[(s+1)%3] (acquire), reads (s+1, k0);
    //    slot s+1 is not written during iter s (writes go to s+2).
    //  * each thread arrives empty[s%3] after its LAST smem read of stage s.
    for (int s = 0; s < S; s++) {
        int pn = s + NSTAGE - 1;
        if (pn < S) {
            if (pn >= NSTAGE)
                MBAR_WAIT(mb_empty + (pn % NSTAGE) * 8,
                          (uint32_t)((pn / NSTAGE - 1) & 1));
            load_stage(sb0 + (pn % NSTAGE) * STAGE_BYTES, aptr,
                       Bmat + (size_t)(pn * KC) * UDIM + n0, tid);
            #pragma unroll
            for (int i = 0; i < 8; i++) aptr[i] += KC;
            CP_ARRIVE(mb_full + (pn % NSTAGE) * 8);
        }

        const uint32_t stgS  = sb0 + (s % NSTAGE) * STAGE_BYTES;
        const uint32_t stgS1 = sb0 + ((s + 1) % NSTAGE) * STAGE_BYTES;
        const uint32_t* bBS  = (const uint32_t*)(smem + SMEM_STAGE0 +
                               (s % NSTAGE) * STAGE_BYTES + A_BYTES) + boff;
        const uint32_t* bBS1 = (const uint32_t*)(smem + SMEM_STAGE0 +
                               ((s + 1) % NSTAGE) * STAGE_BYTES + A_BYTES) + boff;

        // k8 = 0..2: prefetch k8+1 from stage s, mma k8
        #pragma unroll
        for (int k8 = 0; k8 < KC / 8 - 1; k8++) {
            const int cur = k8 & 1;
            const int nxt = cur ^ 1;
            frags(nxt, stgS, bBS, (k8 + 1) * 8);
            #pragma unroll
            for (int mf = 0; mf < 4; mf++)
                #pragma unroll
                for (int jf = 0; jf < 8; jf++)
                    mma8(acc[mf][jf], af[cur][mf], bf[cur][jf]);
        }
        // k8 = 3: tail prefetch (stage s+1, k0), release stage s, mma k3
        {
            const int cur = (KC / 8 - 1) & 1;   // 1
            const int nxt = cur ^ 1;
            if (s + 1 < S) {
                MBAR_WAIT(mb_full + ((s + 1) % NSTAGE) * 8,
                          (uint32_t)(((s + 1) / NSTAGE) & 1));
                frags(nxt, stgS1, bBS1, 0);
            }
            MBAR_ARRIVE(mb_empty + (s % NSTAGE) * 8);  // last stage-s read done
            #pragma unroll
            for (int mf = 0; mf < 4; mf++)
                #pragma unroll
                for (int jf = 0; jf < 8; jf++)
                    mma8(acc[mf][jf], af[cur][mf], bf[cur][jf]);
        }
    }

    // ---- epilogue: BN + ReLU, write out ----
    const float* al = (const float*)(smem + SMEM_ALPHA);
    const float* be = (const float*)(smem + SMEM_BETA);
    #pragma unroll
    for (int mf = 0; mf < 4; mf++) {
        int r0 = mb0 + wm * 64 + mf * 16 + g;   // and r0+8
        float* orow0;
        float* orow1;
        if (MODE) {
            orow0 = out + ((size_t)r0 * L2DIM + l) * UDIM;
            orow1 = out + ((size_t)(r0 + 8) * L2DIM + l) * UDIM;
        } else {
            orow0 = out + (size_t)r0 * UDIM;
            orow1 = out + (size_t)(r0 + 8) * UDIM;
        }
        #pragma unroll
        for (int jf = 0; jf < 8; jf++) {
            int cl = wn * 64 + jf * 8 + 2 * tg;
            float a0 = al[cl], a1 = al[cl + 1];
            float e0 = be[cl], e1 = be[cl + 1];
            float2 v0, v1;
            v0.x = fmaxf(acc[mf][jf][0] * a0 + e0, 0.f);
            v0.y = fmaxf(acc[mf][jf][1] * a1 + e1, 0.f);
            v1.x = fmaxf(acc[mf][jf][2] * a0 + e0, 0.f);
            v1.y = fmaxf(acc[mf][jf][3] * a1 + e1, 0.f);
            *(float2*)(orow0 + n0 + cl) = v0;
            *(float2*)(orow1 + n0 + cl) = v1;
        }
    }
}

// ---------------------------------------------------------------------------
extern "C" void kernel_launch(void* const* d_in, const int* in_sizes, int n_in,
                              void* d_out, int out_size)
{
    const float* x      = (const float*)d_in[0];
    const float* conv_w = (const float*)d_in[1];
    const float* conv_b = (const float*)d_in[2];
    const float* g1     = (const float*)d_in[3];
    const float* b1     = (const float*)d_in[4];
    const float* m1     = (const float*)d_in[5];
    const float* v1     = (const float*)d_in[6];
    const float* lw     = (const float*)d_in[7];
    const float* lb     = (const float*)d_in[8];
    const float* g2     = (const float*)d_in[9];
    const float* b2     = (const float*)d_in[10];
    const float* m2     = (const float*)d_in[11];
    const float* v2     = (const float*)d_in[12];
    float* z = (float*)d_out;

    static bool attr_set = false;
    if (!attr_set) {
        cudaFuncSetAttribute(gemm_mma<0>,
            cudaFuncAttributeMaxDynamicSharedMemorySize, SMEM_TOTAL);
        cudaFuncSetAttribute(gemm_mma<1>,
            cudaFuncAttributeMaxDynamicSharedMemorySize, SMEM_TOTAL);
        cudaFuncSetAttribute(gemm_mma<0>,
            cudaFuncAttributePreferredSharedMemoryCarveout, 100);
        cudaFuncSetAttribute(gemm_mma<1>,
            cudaFuncAttributePreferredSharedMemoryCarveout, 100);
        attr_set = true;
    }

    // Stage 1: M=130048 (1016 tiles of 128), N=256 (2 tiles), K=320
    gemm_mma<0><<<dim3(1016, 2, 1), 128, SMEM_TOTAL>>>(
        x, conv_w, conv_b, g1, b1, m1, v1, nullptr);

    // Stage 2: per-l GEMMs, M=256 (2 tiles), N=256 (2 tiles), K=1280, l=504
    gemm_mma<1><<<dim3(2, 2, L2DIM), 128, SMEM_TOTAL>>>(
        nullptr, lw, lb, g2, b2, m2, v2, z);
}